// round 7
// baseline (speedup 1.0000x reference)
#include <cuda_runtime.h>
#include <cuda_bf16.h>
#include <math.h>

#define NMAX 100000
#define EMAX 1600000
#define GMAX 256
#define HEADSN 4
#define SCAN_CHUNK 512

// ---------------- scratch ----------------
__device__ __align__(16) float g_A[(size_t)NMAX * 128];
__device__ __align__(16) float g_B[(size_t)NMAX * 128];
__device__ __align__(16) float g_C[(size_t)NMAX * 128];
__device__ __align__(16) float g_dis[NMAX];
__device__ __align__(16) int   g_deg[NMAX];
__device__ __align__(16) int   g_rowptr[NMAX + 1];
__device__ __align__(16) int   g_cursor[NMAX];
__device__ __align__(16) int2  g_pack[EMAX];              // (src, bits(dis[src]))
__device__ __align__(16) int   g_blksum[1024];
__device__ __align__(16) float g_ss[NMAX * HEADSN];
__device__ __align__(16) float g_sd[NMAX * HEADSN];
__device__ __align__(16) float g_m[NMAX * HEADSN];
__device__ __align__(16) float g_ws[NMAX * HEADSN];
__device__ __align__(16) float g_mean[128];               // zero-init; bn_final self-resets
__device__ __align__(16) float g_sq[128];
__device__ __align__(16) float g_scale[128];
__device__ __align__(16) float g_shift[128];
__device__ __align__(16) float g_cnt[GMAX];

__device__ __forceinline__ float lrelu(float v) { return v > 0.f ? v : 0.2f * v; }
__device__ __forceinline__ unsigned f2tf(float f) {
    unsigned u; asm("cvt.rna.tf32.f32 %0, %1;" : "=r"(u) : "f"(f)); return u;
}

// ---------------- CSR build ----------------
__global__ void k_deg_zero(int* deg, int n) {
    int i = blockIdx.x * blockDim.x + threadIdx.x;
    if (i < n) deg[i] = 0;
}
__global__ void k_deg_count(const int* __restrict__ colp, int* deg, int E) {
    int i = blockIdx.x * blockDim.x + threadIdx.x;
    if (i < E) atomicAdd(&deg[colp[i]], 1);
}
__global__ void k_scan1(const int* __restrict__ deg, int* blksum, int n) {
    __shared__ int sh[SCAN_CHUNK];
    int i = blockIdx.x * SCAN_CHUNK + threadIdx.x;
    sh[threadIdx.x] = (i < n) ? deg[i] : 0;
    __syncthreads();
    for (int off = SCAN_CHUNK / 2; off > 0; off >>= 1) {
        if (threadIdx.x < off) sh[threadIdx.x] += sh[threadIdx.x + off];
        __syncthreads();
    }
    if (threadIdx.x == 0) blksum[blockIdx.x] = sh[0];
}
__global__ void k_scan2(int* blksum, int nb, int* rowptr_n) {
    __shared__ int sh[1024];
    int tid = threadIdx.x;
    int v = (tid < nb) ? blksum[tid] : 0;
    sh[tid] = v;
    __syncthreads();
    for (int off = 1; off < 1024; off <<= 1) {
        int t = (tid >= off) ? sh[tid - off] : 0;
        __syncthreads();
        sh[tid] += t;
        __syncthreads();
    }
    if (tid < nb) blksum[tid] = sh[tid] - v;   // exclusive
    if (tid == 0) *rowptr_n = sh[1023];        // total E
}
__global__ void k_scan3_dis(const int* __restrict__ deg, const int* __restrict__ blksum,
                            int* rowptr, int* cursor, float* dis, int n) {
    __shared__ int sh[SCAN_CHUNK];
    int i = blockIdx.x * SCAN_CHUNK + threadIdx.x;
    int v = (i < n) ? deg[i] : 0;
    sh[threadIdx.x] = v;
    __syncthreads();
    for (int off = 1; off < SCAN_CHUNK; off <<= 1) {
        int t = (threadIdx.x >= off) ? sh[threadIdx.x - off] : 0;
        __syncthreads();
        sh[threadIdx.x] += t;
        __syncthreads();
    }
    if (i < n) {
        int excl = blksum[blockIdx.x] + sh[threadIdx.x] - v;
        rowptr[i] = excl;
        cursor[i] = excl;
        dis[i] = rsqrtf(1.0f + (float)v);
    }
}
__global__ void k_csr_fill(const int* __restrict__ rowp, const int* __restrict__ colp,
                           const float* __restrict__ dis, int* cursor, int2* pack, int E) {
    int e = blockIdx.x * blockDim.x + threadIdx.x;
    if (e >= E) return;
    int c = colp[e];
    int r = rowp[e];
    int pos = atomicAdd(&cursor[c], 1);
    pack[pos] = make_int2(r, __float_as_int(__ldg(dis + r)));
}

// ---------------- split-TF32 GEMM: out = affine?(X) @ W (+bias) ----------------
template <int DIN, int DOUT, bool BIAS, bool AFFINE>
__global__ void k_gemm(const float* __restrict__ X, const float* __restrict__ W,
                       const float* __restrict__ bias,
                       const float* __restrict__ sc_, const float* __restrict__ sh_,
                       float* __restrict__ out, int n) {
    constexpr int NT = (DOUT >= 128) ? 64 : 128;
    constexpr int KT = (DIN < 32) ? DIN : 32;
    constexpr int NW = NT / 16;
    constexpr int XS = KT + 4;
    constexpr int WS = DOUT + 4;
    __shared__ unsigned Xh[NT * XS];
    __shared__ unsigned Xl[NT * XS];
    __shared__ unsigned Wh[KT * WS];
    __shared__ unsigned Wl[KT * WS];

    const int tid = threadIdx.x;
    const int wid = tid >> 5, lane = tid & 31;
    const int g = lane >> 2, tig = lane & 3;
    const int nsub = wid % NW, cgp = wid / NW;
    const int base = blockIdx.x * NT;

    float acc[8][4];
#pragma unroll
    for (int i = 0; i < 8; ++i)
#pragma unroll
        for (int j = 0; j < 4; ++j) acc[i][j] = 0.f;

    for (int kt = 0; kt < DIN; kt += KT) {
        for (int i = tid; i < NT * (KT / 4); i += 256) {
            int r = i / (KT / 4), c = i % (KT / 4);
            int node = base + r;
            float4 v = make_float4(0.f, 0.f, 0.f, 0.f);
            if (node < n) v = ((const float4*)X)[(size_t)node * (DIN / 4) + kt / 4 + c];
            if (AFFINE) {
                float4 sc = __ldg((const float4*)sc_ + kt / 4 + c);
                float4 sh = __ldg((const float4*)sh_ + kt / 4 + c);
                v.x = v.x * sc.x + sh.x; v.y = v.y * sc.y + sh.y;
                v.z = v.z * sc.z + sh.z; v.w = v.w * sc.w + sh.w;
            }
            unsigned* dh = &Xh[r * XS + c * 4];
            unsigned* dl = &Xl[r * XS + c * 4];
            unsigned h0 = f2tf(v.x), h1 = f2tf(v.y), h2 = f2tf(v.z), h3 = f2tf(v.w);
            dh[0] = h0; dh[1] = h1; dh[2] = h2; dh[3] = h3;
            dl[0] = f2tf(v.x - __uint_as_float(h0));
            dl[1] = f2tf(v.y - __uint_as_float(h1));
            dl[2] = f2tf(v.z - __uint_as_float(h2));
            dl[3] = f2tf(v.w - __uint_as_float(h3));
        }
        for (int i = tid; i < KT * (DOUT / 4); i += 256) {
            int r = i / (DOUT / 4), c = i % (DOUT / 4);
            float4 v = ((const float4*)W)[(size_t)(kt + r) * (DOUT / 4) + c];
            unsigned* dh = &Wh[r * WS + c * 4];
            unsigned* dl = &Wl[r * WS + c * 4];
            unsigned h0 = f2tf(v.x), h1 = f2tf(v.y), h2 = f2tf(v.z), h3 = f2tf(v.w);
            dh[0] = h0; dh[1] = h1; dh[2] = h2; dh[3] = h3;
            dl[0] = f2tf(v.x - __uint_as_float(h0));
            dl[1] = f2tf(v.y - __uint_as_float(h1));
            dl[2] = f2tf(v.z - __uint_as_float(h2));
            dl[3] = f2tf(v.w - __uint_as_float(h3));
        }
        __syncthreads();
#pragma unroll
        for (int ks = 0; ks < KT; ks += 8) {
            int r0 = nsub * 16 + g;
            unsigned ah0 = Xh[r0 * XS + ks + tig];
            unsigned ah1 = Xh[(r0 + 8) * XS + ks + tig];
            unsigned ah2 = Xh[r0 * XS + ks + tig + 4];
            unsigned ah3 = Xh[(r0 + 8) * XS + ks + tig + 4];
            unsigned al0 = Xl[r0 * XS + ks + tig];
            unsigned al1 = Xl[(r0 + 8) * XS + ks + tig];
            unsigned al2 = Xl[r0 * XS + ks + tig + 4];
            unsigned al3 = Xl[(r0 + 8) * XS + ks + tig + 4];
#pragma unroll
            for (int nb = 0; nb < 8; ++nb) {
                int col = cgp * 64 + nb * 8 + g;
                unsigned bh0 = Wh[(ks + tig) * WS + col];
                unsigned bh1 = Wh[(ks + tig + 4) * WS + col];
                unsigned bl0 = Wl[(ks + tig) * WS + col];
                unsigned bl1 = Wl[(ks + tig + 4) * WS + col];
                asm volatile(
                    "mma.sync.aligned.m16n8k8.row.col.f32.tf32.tf32.f32 "
                    "{%0,%1,%2,%3}, {%4,%5,%6,%7}, {%8,%9}, {%0,%1,%2,%3};"
                    : "+f"(acc[nb][0]), "+f"(acc[nb][1]), "+f"(acc[nb][2]), "+f"(acc[nb][3])
                    : "r"(ah0), "r"(ah1), "r"(ah2), "r"(ah3), "r"(bh0), "r"(bh1));
                asm volatile(
                    "mma.sync.aligned.m16n8k8.row.col.f32.tf32.tf32.f32 "
                    "{%0,%1,%2,%3}, {%4,%5,%6,%7}, {%8,%9}, {%0,%1,%2,%3};"
                    : "+f"(acc[nb][0]), "+f"(acc[nb][1]), "+f"(acc[nb][2]), "+f"(acc[nb][3])
                    : "r"(ah0), "r"(ah1), "r"(ah2), "r"(ah3), "r"(bl0), "r"(bl1));
                asm volatile(
                    "mma.sync.aligned.m16n8k8.row.col.f32.tf32.tf32.f32 "
                    "{%0,%1,%2,%3}, {%4,%5,%6,%7}, {%8,%9}, {%0,%1,%2,%3};"
                    : "+f"(acc[nb][0]), "+f"(acc[nb][1]), "+f"(acc[nb][2]), "+f"(acc[nb][3])
                    : "r"(al0), "r"(al1), "r"(al2), "r"(al3), "r"(bh0), "r"(bh1));
            }
        }
        __syncthreads();
    }
    int node0 = base + nsub * 16 + g;
#pragma unroll
    for (int nb = 0; nb < 8; ++nb) {
        int col = cgp * 64 + nb * 8 + 2 * tig;
        float b0 = 0.f, b1 = 0.f;
        if (BIAS) { b0 = __ldg(bias + col); b1 = __ldg(bias + col + 1); }
        if (node0 < n) {
            float2 v = make_float2(acc[nb][0] + b0, acc[nb][1] + b1);
            *(float2*)(out + (size_t)node0 * DOUT + col) = v;
        }
        if (node0 + 8 < n) {
            float2 v = make_float2(acc[nb][2] + b0, acc[nb][3] + b1);
            *(float2*)(out + (size_t)(node0 + 8) * DOUT + col) = v;
        }
    }
}

// ---------------- BatchNorm ----------------
template <int DOUT>
__global__ void k_bn_partial(const float* __restrict__ src, float* mean, float* sq, int n) {
    constexpr int LPC = 256 / DOUT;
    constexpr int NPB = 64;
    int col = threadIdx.x % DOUT, sub = threadIdx.x / DOUT;
    int base = blockIdx.x * NPB;
    int end = base + NPB; if (end > n) end = n;
    float s = 0.f, q = 0.f;
    for (int nn = base + sub; nn < end; nn += LPC) {
        float v = src[(size_t)nn * DOUT + col];
        s += v; q += v * v;
    }
    __shared__ float sh[512];
    sh[threadIdx.x] = s; sh[256 + threadIdx.x] = q;
    __syncthreads();
    if (sub == 0) {
        for (int k = 1; k < LPC; ++k) { s += sh[k * DOUT + col]; q += sh[256 + k * DOUT + col]; }
        atomicAdd(mean + col, s);
        atomicAdd(sq + col, q);
    }
}
template <int DOUT>
__global__ void k_bn_final(float* mean, float* sq,
                           const float* __restrict__ g, const float* __restrict__ b,
                           float* scale, float* shift, int n) {
    int c = threadIdx.x;
    if (c >= DOUT) return;
    float inv = 1.0f / (float)n;
    float mu = mean[c] * inv;
    float var = sq[c] * inv - mu * mu;
    float sc = g[c] * rsqrtf(var + 1e-5f);
    scale[c] = sc;
    shift[c] = b[c] - mu * sc;
    mean[c] = 0.f;
    sq[c] = 0.f;
}

// ---------------- GCN gather: two-phase batch-8 loads (MLP=8) ----------------
template <int TPN, bool BIASP, bool AFFINE, bool RELUIN>
__global__ void __launch_bounds__(256)
k_gather(const int* __restrict__ rowptr, const int2* __restrict__ pack,
         const float* __restrict__ dis, const float* __restrict__ h,
         const float* __restrict__ bias,
         const float* __restrict__ sc_, const float* __restrict__ sh_,
         float* __restrict__ out, int n) {
    constexpr int BB = 8;
    int t = blockIdx.x * 256 + threadIdx.x;
    int node = t / TPN, sub = t % TPN;
    if (node >= n) return;
    float4 sc, sh;
    if (AFFINE) { sc = __ldg((const float4*)sc_ + sub); sh = __ldg((const float4*)sh_ + sub); }
    float dc = __ldg(dis + node);
    float4 acc = make_float4(0.f, 0.f, 0.f, 0.f);
    if (BIASP) acc = __ldg((const float4*)bias + sub);
    {
        float4 v = __ldg((const float4*)h + (size_t)node * TPN + sub);
        if (AFFINE) {
            v.x = v.x * sc.x + sh.x; v.y = v.y * sc.y + sh.y;
            v.z = v.z * sc.z + sh.z; v.w = v.w * sc.w + sh.w;
        }
        if (RELUIN) { v.x = lrelu(v.x); v.y = lrelu(v.y); v.z = lrelu(v.z); v.w = lrelu(v.w); }
        float w = dc * dc;
        acc.x += v.x * w; acc.y += v.y * w; acc.z += v.z * w; acc.w += v.w * w;
    }
    int s0 = __ldg(rowptr + node), s1 = __ldg(rowptr + node + 1);
    for (int bjs = s0; bjs < s1; bjs += BB) {
        int2 p[BB];
#pragma unroll
        for (int q = 0; q < BB; ++q) {
            int j = bjs + q;
            p[q] = (j < s1) ? __ldg(pack + j) : make_int2(node, 0);  // w=0 dummy
        }
        float4 v[BB];
#pragma unroll
        for (int q = 0; q < BB; ++q)
            v[q] = __ldg((const float4*)h + (size_t)p[q].x * TPN + sub);
#pragma unroll
        for (int q = 0; q < BB; ++q) {
            float w = __int_as_float(p[q].y) * dc;
            float4 u = v[q];
            if (AFFINE) {
                u.x = u.x * sc.x + sh.x; u.y = u.y * sc.y + sh.y;
                u.z = u.z * sc.z + sh.z; u.w = u.w * sc.w + sh.w;
            }
            if (RELUIN) { u.x = lrelu(u.x); u.y = lrelu(u.y); u.z = lrelu(u.z); u.w = lrelu(u.w); }
            acc.x += u.x * w; acc.y += u.y * w; acc.z += u.z * w; acc.w += u.w * w;
        }
    }
    ((float4*)out)[(size_t)node * TPN + sub] = acc;
}

// ---------------- GAT ----------------
template <int D, int H>
__global__ void k_gat_scores(const float* __restrict__ h2,
                             const float* __restrict__ a_src, const float* __restrict__ a_dst,
                             float* __restrict__ ss, float* __restrict__ sd, int n) {
    constexpr int C  = D / H;
    constexpr int L  = D / 4;
    constexpr int GP = C / 4;
    int warp = (blockIdx.x * blockDim.x + threadIdx.x) >> 5;
    int lane = threadIdx.x & 31;
    if (warp >= n) return;
    float ps = 0.f, pd = 0.f;
    int head = 0;
    if (lane < L) {
        float4 v = ((const float4*)h2)[(size_t)warp * L + lane];
        head = lane / GP;
        int o = head * C + (lane % GP) * 4;
        ps = v.x * __ldg(a_src + o) + v.y * __ldg(a_src + o + 1)
           + v.z * __ldg(a_src + o + 2) + v.w * __ldg(a_src + o + 3);
        pd = v.x * __ldg(a_dst + o) + v.y * __ldg(a_dst + o + 1)
           + v.z * __ldg(a_dst + o + 2) + v.w * __ldg(a_dst + o + 3);
    }
#pragma unroll
    for (int off = GP / 2; off > 0; off >>= 1) {
        ps += __shfl_xor_sync(0xffffffff, ps, off);
        pd += __shfl_xor_sync(0xffffffff, pd, off);
    }
    if (lane < L && (lane % GP) == 0) {
        ss[(size_t)warp * H + head] = ps;
        sd[(size_t)warp * H + head] = pd;
    }
}

#define NEG_BIG -1e30f
__device__ __forceinline__ void online_upd(float& m, float& s, float e) {
    float nm = fmaxf(m, e);
    s = s * __expf(m - nm) + __expf(e - nm);
    m = nm;
}
__device__ __forceinline__ void online_comb(float& m, float& s, float m2, float s2) {
    float nm = fmaxf(m, m2);
    s = s * __expf(m - nm) + s2 * __expf(m2 - nm);
    m = nm;
}

__global__ void k_gat_softmax(const int* __restrict__ rowptr, const int2* __restrict__ pack,
                              const float* __restrict__ ss, const float* __restrict__ sd,
                              float* __restrict__ mout, float* __restrict__ wsout, int n) {
    int warp = (blockIdx.x * blockDim.x + threadIdx.x) >> 5;
    int lane = threadIdx.x & 31;
    if (warp >= n) return;
    float4 sdv = ((const float4*)sd)[warp];
    float4 m = make_float4(NEG_BIG, NEG_BIG, NEG_BIG, NEG_BIG);
    float4 s = make_float4(0.f, 0.f, 0.f, 0.f);
    if (lane == 0) {
        float4 e = ((const float4*)ss)[warp];
        m.x = lrelu(e.x + sdv.x); m.y = lrelu(e.y + sdv.y);
        m.z = lrelu(e.z + sdv.z); m.w = lrelu(e.w + sdv.w);
        s = make_float4(1.f, 1.f, 1.f, 1.f);
    }
    int s0 = __ldg(rowptr + warp), s1 = __ldg(rowptr + warp + 1);
    for (int j = s0 + lane; j < s1; j += 32) {
        int r = __ldg(pack + j).x;
        float4 e = __ldg((const float4*)ss + r);
        online_upd(m.x, s.x, lrelu(e.x + sdv.x));
        online_upd(m.y, s.y, lrelu(e.y + sdv.y));
        online_upd(m.z, s.z, lrelu(e.z + sdv.z));
        online_upd(m.w, s.w, lrelu(e.w + sdv.w));
    }
#pragma unroll
    for (int off = 16; off > 0; off >>= 1) {
        float m2x = __shfl_xor_sync(0xffffffff, m.x, off);
        float m2y = __shfl_xor_sync(0xffffffff, m.y, off);
        float m2z = __shfl_xor_sync(0xffffffff, m.z, off);
        float m2w = __shfl_xor_sync(0xffffffff, m.w, off);
        float s2x = __shfl_xor_sync(0xffffffff, s.x, off);
        float s2y = __shfl_xor_sync(0xffffffff, s.y, off);
        float s2z = __shfl_xor_sync(0xffffffff, s.z, off);
        float s2w = __shfl_xor_sync(0xffffffff, s.w, off);
        online_comb(m.x, s.x, m2x, s2x);
        online_comb(m.y, s.y, m2y, s2y);
        online_comb(m.z, s.z, m2z, s2z);
        online_comb(m.w, s.w, m2w, s2w);
    }
    if (lane == 0) {
        ((float4*)mout)[warp] = m;
        ((float4*)wsout)[warp] = s;
    }
}

// fused weighted gather, two-phase batch-8 (invalid -> e=-1e30 -> w=0)
template <int TPN, int H, bool RELU>
__global__ void __launch_bounds__(256)
k_gat_fused(const int* __restrict__ rowptr, const int2* __restrict__ pack,
            const float* __restrict__ ss, const float* __restrict__ sd,
            const float* __restrict__ m_, const float* __restrict__ ws_,
            const float* __restrict__ h2, const float* __restrict__ bias,
            const float* __restrict__ resraw,
            const float* __restrict__ sc_, const float* __restrict__ sh_,
            float* __restrict__ out, int n) {
    constexpr int C = TPN * 4 / H;
    constexpr int BB = 8;
    int t = blockIdx.x * 256 + threadIdx.x;
    int node = t / TPN, sub = t % TPN;
    if (node >= n) return;
    int head = (sub * 4) / C;
    float sdv = __ldg(sd + (size_t)node * H + head);
    float m   = __ldg(m_ + (size_t)node * H + head);
    float inv = 1.0f / __ldg(ws_ + (size_t)node * H + head);

    float wsf = __expf(lrelu(__ldg(ss + (size_t)node * H + head) + sdv) - m);
    float4 acc = __ldg((const float4*)h2 + (size_t)node * TPN + sub);
    acc.x *= wsf; acc.y *= wsf; acc.z *= wsf; acc.w *= wsf;

    int s0 = __ldg(rowptr + node), s1 = __ldg(rowptr + node + 1);
    for (int bjs = s0; bjs < s1; bjs += BB) {
        int rr[BB]; bool ok[BB];
#pragma unroll
        for (int q = 0; q < BB; ++q) {
            int j = bjs + q;
            ok[q] = (j < s1);
            rr[q] = ok[q] ? __ldg(pack + j).x : node;
        }
        float ee[BB];
#pragma unroll
        for (int q = 0; q < BB; ++q)
            ee[q] = ok[q] ? __ldg(ss + (size_t)rr[q] * H + head) : NEG_BIG;
        float4 v[BB];
#pragma unroll
        for (int q = 0; q < BB; ++q)
            v[q] = __ldg((const float4*)h2 + (size_t)rr[q] * TPN + sub);
#pragma unroll
        for (int q = 0; q < BB; ++q) {
            float w = __expf(lrelu(ee[q] + sdv) - m);   // 0 for dummies
            acc.x += v[q].x * w; acc.y += v[q].y * w;
            acc.z += v[q].z * w; acc.w += v[q].w * w;
        }
    }
    float4 bv = __ldg((const float4*)bias + sub);
    float4 xr = __ldg((const float4*)resraw + (size_t)node * TPN + sub);
    float4 sc = __ldg((const float4*)sc_ + sub);
    float4 sh = __ldg((const float4*)sh_ + sub);
    float4 o;
    o.x = acc.x * inv + bv.x + (xr.x * sc.x + sh.x);
    o.y = acc.y * inv + bv.y + (xr.y * sc.y + sh.y);
    o.z = acc.z * inv + bv.z + (xr.z * sc.z + sh.z);
    o.w = acc.w * inv + bv.w + (xr.w * sc.w + sh.w);
    if (RELU) { o.x = lrelu(o.x); o.y = lrelu(o.y); o.z = lrelu(o.z); o.w = lrelu(o.w); }
    ((float4*)out)[(size_t)node * TPN + sub] = o;
}

// ---------------- pooling ----------------
__global__ void k_pool_clear(float* out, float* cnt, int total, int G) {
    int i = blockIdx.x * blockDim.x + threadIdx.x;
    if (i < total) out[i] = 0.f;
    if (i < G) cnt[i] = 0.f;
}
__global__ void k_pool_sum(const float* __restrict__ x, const int* __restrict__ batch,
                           const float* __restrict__ sc_, const float* __restrict__ sh_,
                           float* __restrict__ out, float* cnt, int n) {
    int idx = blockIdx.x * blockDim.x + threadIdx.x;
    if (idx >= n * 16) return;
    int nn = idx / 16, cg = idx % 16;
    int g = __ldg(batch + nn);
    float4 v = ((const float4*)x)[idx];
    float4 sc = __ldg((const float4*)sc_ + cg);
    float4 sh = __ldg((const float4*)sh_ + cg);
    v.x = v.x * sc.x + sh.x; v.y = v.y * sc.y + sh.y;
    v.z = v.z * sc.z + sh.z; v.w = v.w * sc.w + sh.w;
    atomicAdd((float4*)out + (size_t)g * 16 + cg, v);
    if (cg == 0) atomicAdd(&cnt[g], 1.0f);
}
__global__ void k_pool_div(float* out, const float* cnt, int total) {
    int i = blockIdx.x * blockDim.x + threadIdx.x;
    if (i >= total) return;
    int g = i / 64;
    out[i] /= fmaxf(cnt[g], 1.0f);
}

// ---------------- host ----------------
static inline int GRID(long long t) { return (int)((t + 255) / 256); }

extern "C" void kernel_launch(void* const* d_in, const int* in_sizes, int n_in,
                              void* d_out, int out_size) {
    const float* x     = (const float*)d_in[0];
    const int*   ei    = (const int*)d_in[1];
    const int*   batch = (const int*)d_in[2];
    const int n = in_sizes[0] / 16;
    const int E = in_sizes[1] / 2;
    const int* rowp = ei;
    const int* colp = ei + E;

    const float* gcn_w[4] = {(const float*)d_in[3], (const float*)d_in[7],
                             (const float*)d_in[11], (const float*)d_in[15]};
    const float* gcn_b[4] = {(const float*)d_in[4], (const float*)d_in[8],
                             (const float*)d_in[12], (const float*)d_in[16]};
    const float* bn_g[4]  = {(const float*)d_in[5], (const float*)d_in[9],
                             (const float*)d_in[13], (const float*)d_in[17]};
    const float* bn_b[4]  = {(const float*)d_in[6], (const float*)d_in[10],
                             (const float*)d_in[14], (const float*)d_in[18]};
    const float* gat_w0    = (const float*)d_in[19];
    const float* gat_asrc0 = (const float*)d_in[20];
    const float* gat_adst0 = (const float*)d_in[21];
    const float* gat_b0    = (const float*)d_in[22];
    const float* gat_w2    = (const float*)d_in[23];
    const float* gat_asrc2 = (const float*)d_in[24];
    const float* gat_adst2 = (const float*)d_in[25];
    const float* gat_b2    = (const float*)d_in[26];

    float *A, *B, *C, *dis, *ss, *sd, *mM, *wsum, *mean, *sq, *scale, *shift, *cnt;
    int *deg, *rowptr, *cursor, *blksum;
    int2* pack;
    cudaGetSymbolAddress((void**)&A, g_A);
    cudaGetSymbolAddress((void**)&B, g_B);
    cudaGetSymbolAddress((void**)&C, g_C);
    cudaGetSymbolAddress((void**)&dis, g_dis);
    cudaGetSymbolAddress((void**)&deg, g_deg);
    cudaGetSymbolAddress((void**)&rowptr, g_rowptr);
    cudaGetSymbolAddress((void**)&cursor, g_cursor);
    cudaGetSymbolAddress((void**)&pack, g_pack);
    cudaGetSymbolAddress((void**)&blksum, g_blksum);
    cudaGetSymbolAddress((void**)&ss, g_ss);
    cudaGetSymbolAddress((void**)&sd, g_sd);
    cudaGetSymbolAddress((void**)&mM, g_m);
    cudaGetSymbolAddress((void**)&wsum, g_ws);
    cudaGetSymbolAddress((void**)&mean, g_mean);
    cudaGetSymbolAddress((void**)&sq, g_sq);
    cudaGetSymbolAddress((void**)&scale, g_scale);
    cudaGetSymbolAddress((void**)&shift, g_shift);
    cudaGetSymbolAddress((void**)&cnt, g_cnt);
    float* out = (float*)d_out;

    // ---- CSR build (packed) ----
    const int nb = (n + SCAN_CHUNK - 1) / SCAN_CHUNK;
    k_deg_zero<<<GRID(n), 256>>>(deg, n);
    k_deg_count<<<GRID(E), 256>>>(colp, deg, E);
    k_scan1<<<nb, SCAN_CHUNK>>>(deg, blksum, n);
    k_scan2<<<1, 1024>>>(blksum, nb, rowptr + n);
    k_scan3_dis<<<nb, SCAN_CHUNK>>>(deg, blksum, rowptr, cursor, dis, n);
    k_csr_fill<<<GRID(E), 256>>>(rowp, colp, dis, cursor, pack, E);

    // ----- layer 0 -----
    k_gather<4, false, false, false><<<(n + 63) / 64, 256>>>(
        rowptr, pack, dis, x, nullptr, nullptr, nullptr, C, n);
    k_gemm<16, 64, true, false><<<(n + 127) / 128, 256>>>(
        C, gcn_w[0], gcn_b[0], nullptr, nullptr, B, n);
    k_bn_partial<64><<<(n + 63) / 64, 256>>>(B, mean, sq, n);
    k_bn_final<64><<<1, 64>>>(mean, sq, bn_g[0], bn_b[0], scale, shift, n);
    k_gemm<64, 64, false, true><<<(n + 127) / 128, 256>>>(
        B, gat_w0, nullptr, scale, shift, A, n);
    k_gat_scores<64, 4><<<(n + 3) / 4, 128>>>(A, gat_asrc0, gat_adst0, ss, sd, n);
    k_gat_softmax<<<(n + 7) / 8, 256>>>(rowptr, pack, ss, sd, mM, wsum, n);
    k_gat_fused<16, 4, true><<<(n + 15) / 16, 256>>>(
        rowptr, pack, ss, sd, mM, wsum, A, gat_b0, B, scale, shift, B, n);

    // ----- layer 1 -----
    k_gather<16, false, false, false><<<(n + 15) / 16, 256>>>(
        rowptr, pack, dis, B, nullptr, nullptr, nullptr, C, n);
    k_gemm<64, 128, true, false><<<(n + 63) / 64, 256>>>(
        C, gcn_w[1], gcn_b[1], nullptr, nullptr, A, n);
    k_bn_partial<128><<<(n + 63) / 64, 256>>>(A, mean, sq, n);
    k_bn_final<128><<<1, 128>>>(mean, sq, bn_g[1], bn_b[1], scale, shift, n);

    // ----- layer 2 (L1 bn+relu folded into gather input) -----
    k_gather<32, false, true, true><<<(n + 7) / 8, 256>>>(
        rowptr, pack, dis, A, nullptr, scale, shift, C, n);
    k_gemm<128, 128, true, false><<<(n + 63) / 64, 256>>>(
        C, gcn_w[2], gcn_b[2], nullptr, nullptr, B, n);
    k_bn_partial<128><<<(n + 63) / 64, 256>>>(B, mean, sq, n);
    k_bn_final<128><<<1, 128>>>(mean, sq, bn_g[2], bn_b[2], scale, shift, n);
    k_gemm<128, 128, false, true><<<(n + 63) / 64, 256>>>(
        B, gat_w2, nullptr, scale, shift, A, n);
    k_gat_scores<128, 4><<<(n + 3) / 4, 128>>>(A, gat_asrc2, gat_adst2, ss, sd, n);
    k_gat_softmax<<<(n + 7) / 8, 256>>>(rowptr, pack, ss, sd, mM, wsum, n);
    k_gat_fused<32, 4, true><<<(n + 7) / 8, 256>>>(
        rowptr, pack, ss, sd, mM, wsum, A, gat_b2, B, scale, shift, B, n);

    // ----- layer 3 -----
    k_gemm<128, 64, false, false><<<(n + 127) / 128, 256>>>(
        B, gcn_w[3], nullptr, nullptr, nullptr, A, n);
    k_gather<16, true, false, false><<<(n + 15) / 16, 256>>>(
        rowptr, pack, dis, A, gcn_b[3], nullptr, nullptr, C, n);
    k_bn_partial<64><<<(n + 63) / 64, 256>>>(C, mean, sq, n);
    k_bn_final<64><<<1, 64>>>(mean, sq, bn_g[3], bn_b[3], scale, shift, n);

    // ----- pooling -----
    const int G = out_size / 64;
    k_pool_clear<<<GRID(out_size), 256>>>(out, cnt, out_size, G);
    k_pool_sum<<<GRID((long long)n * 16), 256>>>(C, batch, scale, shift, out, cnt, n);
    k_pool_div<<<GRID(out_size), 256>>>(out, cnt, out_size);
}

// round 8
// speedup vs baseline: 1.0680x; 1.0680x over previous
#include <cuda_runtime.h>
#include <cuda_bf16.h>
#include <cuda_fp16.h>
#include <math.h>

#define NMAX 100000
#define EMAX 1600000
#define GMAX 256
#define HEADSN 4
#define SCAN_CHUNK 512

// ---------------- scratch ----------------
__device__ __align__(16) float  g_A[(size_t)NMAX * 128];
__device__ __align__(16) float  g_B[(size_t)NMAX * 128];
__device__ __align__(16) float  g_C[(size_t)NMAX * 128];
__device__ __align__(16) __half g_H[(size_t)NMAX * 128];   // half feature buffer (d<=128)
__device__ __align__(16) __half g_H2[(size_t)NMAX * 64];   // half feature buffer (d<=64)
__device__ __align__(16) float  g_dis[NMAX];
__device__ __align__(16) int    g_deg[NMAX];
__device__ __align__(16) int    g_rowptr[NMAX + 1];
__device__ __align__(16) int    g_cursor[NMAX];
__device__ __align__(16) int2   g_pack[EMAX];              // (src, bits(dis[src]))
__device__ __align__(16) int    g_blksum[1024];
__device__ __align__(16) float  g_ss[NMAX * HEADSN];
__device__ __align__(16) float  g_sd[NMAX * HEADSN];
__device__ __align__(16) float  g_m[NMAX * HEADSN];
__device__ __align__(16) float  g_ws[NMAX * HEADSN];
__device__ __align__(16) float  g_mean[128];               // zero-init; bn_final self-resets
__device__ __align__(16) float  g_sq[128];
__device__ __align__(16) float  g_scale[128];
__device__ __align__(16) float  g_shift[128];
__device__ __align__(16) float  g_cnt[GMAX];

__device__ __forceinline__ float lrelu(float v) { return v > 0.f ? v : 0.2f * v; }
__device__ __forceinline__ unsigned f2tf(float f) {
    unsigned u; asm("cvt.rna.tf32.f32 %0, %1;" : "=r"(u) : "f"(f)); return u;
}

// load 4 channels (float4) from fp32 or fp16 storage
template <bool HALF>
__device__ __forceinline__ float4 ldrow(const void* h, size_t idx) {
    if (HALF) {
        uint2 u = __ldg((const uint2*)h + idx);
        __half2 a = *reinterpret_cast<__half2*>(&u.x);
        __half2 b = *reinterpret_cast<__half2*>(&u.y);
        float2 fa = __half22float2(a), fb = __half22float2(b);
        return make_float4(fa.x, fa.y, fb.x, fb.y);
    } else {
        return __ldg((const float4*)h + idx);
    }
}
__device__ __forceinline__ void st4half(void* out, size_t idx, float4 o) {
    uint2 up;
    *reinterpret_cast<__half2*>(&up.x) = __floats2half2_rn(o.x, o.y);
    *reinterpret_cast<__half2*>(&up.y) = __floats2half2_rn(o.z, o.w);
    ((uint2*)out)[idx] = up;
}

// ---------------- CSR build ----------------
__global__ void k_deg_zero(int* deg, int n) {
    int i = blockIdx.x * blockDim.x + threadIdx.x;
    if (i < n) deg[i] = 0;
}
__global__ void k_deg_count(const int* __restrict__ colp, int* deg, int E) {
    int i = blockIdx.x * blockDim.x + threadIdx.x;
    if (i < E) atomicAdd(&deg[colp[i]], 1);
}
__global__ void k_scan1(const int* __restrict__ deg, int* blksum, int n) {
    __shared__ int sh[SCAN_CHUNK];
    int i = blockIdx.x * SCAN_CHUNK + threadIdx.x;
    sh[threadIdx.x] = (i < n) ? deg[i] : 0;
    __syncthreads();
    for (int off = SCAN_CHUNK / 2; off > 0; off >>= 1) {
        if (threadIdx.x < off) sh[threadIdx.x] += sh[threadIdx.x + off];
        __syncthreads();
    }
    if (threadIdx.x == 0) blksum[blockIdx.x] = sh[0];
}
// scan3 with scan2 fused: each block reduces its own blksum prefix
__global__ void k_scan3_dis(const int* __restrict__ deg, const int* __restrict__ blksum,
                            int* rowptr, int* cursor, float* dis, int n) {
    __shared__ int sh[SCAN_CHUNK];
    int tid = threadIdx.x, bid = blockIdx.x;
    // base = sum blksum[0..bid)
    int part = 0;
    for (int j = tid; j < bid; j += SCAN_CHUNK) part += __ldg(blksum + j);
    sh[tid] = part;
    __syncthreads();
    for (int off = SCAN_CHUNK / 2; off > 0; off >>= 1) {
        if (tid < off) sh[tid] += sh[tid + off];
        __syncthreads();
    }
    int base = sh[0];
    __syncthreads();
    // inclusive scan of this chunk
    int i = bid * SCAN_CHUNK + tid;
    int v = (i < n) ? deg[i] : 0;
    sh[tid] = v;
    __syncthreads();
    for (int off = 1; off < SCAN_CHUNK; off <<= 1) {
        int t = (tid >= off) ? sh[tid - off] : 0;
        __syncthreads();
        sh[tid] += t;
        __syncthreads();
    }
    if (i < n) {
        int excl = base + sh[tid] - v;
        rowptr[i] = excl;
        cursor[i] = excl;
        dis[i] = rsqrtf(1.0f + (float)v);
        if (i == n - 1) rowptr[n] = excl + v;
    }
}
__global__ void k_csr_fill(const int* __restrict__ rowp, const int* __restrict__ colp,
                           const float* __restrict__ dis, int* cursor, int2* pack, int E) {
    int e = blockIdx.x * blockDim.x + threadIdx.x;
    if (e >= E) return;
    int c = colp[e];
    int r = rowp[e];
    int pos = atomicAdd(&cursor[c], 1);
    pack[pos] = make_int2(r, __float_as_int(__ldg(dis + r)));
}

// ---------------- split-TF32 GEMM: out = affine?(X) @ W (+bias) ----------------
template <int DIN, int DOUT, bool BIAS, bool AFFINE, bool OUTHALF>
__global__ void k_gemm(const float* __restrict__ X, const float* __restrict__ W,
                       const float* __restrict__ bias,
                       const float* __restrict__ sc_, const float* __restrict__ sh_,
                       void* __restrict__ outv, int n) {
    constexpr int NT = (DOUT >= 128) ? 64 : 128;
    constexpr int KT = (DIN < 32) ? DIN : 32;
    constexpr int NW = NT / 16;
    constexpr int XS = KT + 4;
    constexpr int WS = DOUT + 4;
    __shared__ unsigned Xh[NT * XS];
    __shared__ unsigned Xl[NT * XS];
    __shared__ unsigned Wh[KT * WS];
    __shared__ unsigned Wl[KT * WS];

    const int tid = threadIdx.x;
    const int wid = tid >> 5, lane = tid & 31;
    const int g = lane >> 2, tig = lane & 3;
    const int nsub = wid % NW, cgp = wid / NW;
    const int base = blockIdx.x * NT;

    float acc[8][4];
#pragma unroll
    for (int i = 0; i < 8; ++i)
#pragma unroll
        for (int j = 0; j < 4; ++j) acc[i][j] = 0.f;

    for (int kt = 0; kt < DIN; kt += KT) {
        for (int i = tid; i < NT * (KT / 4); i += 256) {
            int r = i / (KT / 4), c = i % (KT / 4);
            int node = base + r;
            float4 v = make_float4(0.f, 0.f, 0.f, 0.f);
            if (node < n) v = ((const float4*)X)[(size_t)node * (DIN / 4) + kt / 4 + c];
            if (AFFINE) {
                float4 sc = __ldg((const float4*)sc_ + kt / 4 + c);
                float4 sh = __ldg((const float4*)sh_ + kt / 4 + c);
                v.x = v.x * sc.x + sh.x; v.y = v.y * sc.y + sh.y;
                v.z = v.z * sc.z + sh.z; v.w = v.w * sc.w + sh.w;
            }
            unsigned* dh = &Xh[r * XS + c * 4];
            unsigned* dl = &Xl[r * XS + c * 4];
            unsigned h0 = f2tf(v.x), h1 = f2tf(v.y), h2 = f2tf(v.z), h3 = f2tf(v.w);
            dh[0] = h0; dh[1] = h1; dh[2] = h2; dh[3] = h3;
            dl[0] = f2tf(v.x - __uint_as_float(h0));
            dl[1] = f2tf(v.y - __uint_as_float(h1));
            dl[2] = f2tf(v.z - __uint_as_float(h2));
            dl[3] = f2tf(v.w - __uint_as_float(h3));
        }
        for (int i = tid; i < KT * (DOUT / 4); i += 256) {
            int r = i / (DOUT / 4), c = i % (DOUT / 4);
            float4 v = ((const float4*)W)[(size_t)(kt + r) * (DOUT / 4) + c];
            unsigned* dh = &Wh[r * WS + c * 4];
            unsigned* dl = &Wl[r * WS + c * 4];
            unsigned h0 = f2tf(v.x), h1 = f2tf(v.y), h2 = f2tf(v.z), h3 = f2tf(v.w);
            dh[0] = h0; dh[1] = h1; dh[2] = h2; dh[3] = h3;
            dl[0] = f2tf(v.x - __uint_as_float(h0));
            dl[1] = f2tf(v.y - __uint_as_float(h1));
            dl[2] = f2tf(v.z - __uint_as_float(h2));
            dl[3] = f2tf(v.w - __uint_as_float(h3));
        }
        __syncthreads();
#pragma unroll
        for (int ks = 0; ks < KT; ks += 8) {
            int r0 = nsub * 16 + g;
            unsigned ah0 = Xh[r0 * XS + ks + tig];
            unsigned ah1 = Xh[(r0 + 8) * XS + ks + tig];
            unsigned ah2 = Xh[r0 * XS + ks + tig + 4];
            unsigned ah3 = Xh[(r0 + 8) * XS + ks + tig + 4];
            unsigned al0 = Xl[r0 * XS + ks + tig];
            unsigned al1 = Xl[(r0 + 8) * XS + ks + tig];
            unsigned al2 = Xl[r0 * XS + ks + tig + 4];
            unsigned al3 = Xl[(r0 + 8) * XS + ks + tig + 4];
#pragma unroll
            for (int nb = 0; nb < 8; ++nb) {
                int col = cgp * 64 + nb * 8 + g;
                unsigned bh0 = Wh[(ks + tig) * WS + col];
                unsigned bh1 = Wh[(ks + tig + 4) * WS + col];
                unsigned bl0 = Wl[(ks + tig) * WS + col];
                unsigned bl1 = Wl[(ks + tig + 4) * WS + col];
                asm volatile(
                    "mma.sync.aligned.m16n8k8.row.col.f32.tf32.tf32.f32 "
                    "{%0,%1,%2,%3}, {%4,%5,%6,%7}, {%8,%9}, {%0,%1,%2,%3};"
                    : "+f"(acc[nb][0]), "+f"(acc[nb][1]), "+f"(acc[nb][2]), "+f"(acc[nb][3])
                    : "r"(ah0), "r"(ah1), "r"(ah2), "r"(ah3), "r"(bh0), "r"(bh1));
                asm volatile(
                    "mma.sync.aligned.m16n8k8.row.col.f32.tf32.tf32.f32 "
                    "{%0,%1,%2,%3}, {%4,%5,%6,%7}, {%8,%9}, {%0,%1,%2,%3};"
                    : "+f"(acc[nb][0]), "+f"(acc[nb][1]), "+f"(acc[nb][2]), "+f"(acc[nb][3])
                    : "r"(ah0), "r"(ah1), "r"(ah2), "r"(ah3), "r"(bl0), "r"(bl1));
                asm volatile(
                    "mma.sync.aligned.m16n8k8.row.col.f32.tf32.tf32.f32 "
                    "{%0,%1,%2,%3}, {%4,%5,%6,%7}, {%8,%9}, {%0,%1,%2,%3};"
                    : "+f"(acc[nb][0]), "+f"(acc[nb][1]), "+f"(acc[nb][2]), "+f"(acc[nb][3])
                    : "r"(al0), "r"(al1), "r"(al2), "r"(al3), "r"(bh0), "r"(bh1));
            }
        }
        __syncthreads();
    }
    int node0 = base + nsub * 16 + g;
#pragma unroll
    for (int nb = 0; nb < 8; ++nb) {
        int col = cgp * 64 + nb * 8 + 2 * tig;
        float b0 = 0.f, b1 = 0.f;
        if (BIAS) { b0 = __ldg(bias + col); b1 = __ldg(bias + col + 1); }
        if (node0 < n) {
            float v0 = acc[nb][0] + b0, v1 = acc[nb][1] + b1;
            if (OUTHALF)
                ((__half2*)outv)[((size_t)node0 * DOUT + col) >> 1] = __floats2half2_rn(v0, v1);
            else
                *(float2*)((float*)outv + (size_t)node0 * DOUT + col) = make_float2(v0, v1);
        }
        if (node0 + 8 < n) {
            float v0 = acc[nb][2] + b0, v1 = acc[nb][3] + b1;
            if (OUTHALF)
                ((__half2*)outv)[((size_t)(node0 + 8) * DOUT + col) >> 1] = __floats2half2_rn(v0, v1);
            else
                *(float2*)((float*)outv + (size_t)(node0 + 8) * DOUT + col) = make_float2(v0, v1);
        }
    }
}

// ---------------- BatchNorm ----------------
template <int DOUT, bool HALF>
__global__ void k_bn_partial(const void* __restrict__ src, float* mean, float* sq, int n) {
    constexpr int LPC = 256 / DOUT;
    constexpr int NPB = 64;
    int col = threadIdx.x % DOUT, sub = threadIdx.x / DOUT;
    int base = blockIdx.x * NPB;
    int end = base + NPB; if (end > n) end = n;
    float s = 0.f, q = 0.f;
    for (int nn = base + sub; nn < end; nn += LPC) {
        float v;
        if (HALF) v = __half2float(((const __half*)src)[(size_t)nn * DOUT + col]);
        else      v = ((const float*)src)[(size_t)nn * DOUT + col];
        s += v; q += v * v;
    }
    __shared__ float sh[512];
    sh[threadIdx.x] = s; sh[256 + threadIdx.x] = q;
    __syncthreads();
    if (sub == 0) {
        for (int k = 1; k < LPC; ++k) { s += sh[k * DOUT + col]; q += sh[256 + k * DOUT + col]; }
        atomicAdd(mean + col, s);
        atomicAdd(sq + col, q);
    }
}
template <int DOUT>
__global__ void k_bn_final(float* mean, float* sq,
                           const float* __restrict__ g, const float* __restrict__ b,
                           float* scale, float* shift, int n) {
    int c = threadIdx.x;
    if (c >= DOUT) return;
    float inv = 1.0f / (float)n;
    float mu = mean[c] * inv;
    float var = sq[c] * inv - mu * mu;
    float sc = g[c] * rsqrtf(var + 1e-5f);
    scale[c] = sc;
    shift[c] = b[c] - mu * sc;
    mean[c] = 0.f;
    sq[c] = 0.f;
}

// ---------------- GCN gather (packed CSR; optional input affine+relu; fp16 input opt) ---
template <int TPN, bool BIASP, bool AFFINE, bool RELUIN, bool INHALF>
__global__ void __launch_bounds__(256)
k_gather(const int* __restrict__ rowptr, const int2* __restrict__ pack,
         const float* __restrict__ dis, const void* __restrict__ h,
         const float* __restrict__ bias,
         const float* __restrict__ sc_, const float* __restrict__ sh_,
         float* __restrict__ out, int n) {
    int t = blockIdx.x * 256 + threadIdx.x;
    int node = t / TPN, sub = t % TPN;
    if (node >= n) return;
    float4 sc, sh;
    if (AFFINE) { sc = __ldg((const float4*)sc_ + sub); sh = __ldg((const float4*)sh_ + sub); }
    float dc = __ldg(dis + node);
    float4 acc = make_float4(0.f, 0.f, 0.f, 0.f);
    if (BIASP) acc = __ldg((const float4*)bias + sub);
    {
        float4 v = ldrow<INHALF>(h, (size_t)node * TPN + sub);
        if (AFFINE) {
            v.x = v.x * sc.x + sh.x; v.y = v.y * sc.y + sh.y;
            v.z = v.z * sc.z + sh.z; v.w = v.w * sc.w + sh.w;
        }
        if (RELUIN) { v.x = lrelu(v.x); v.y = lrelu(v.y); v.z = lrelu(v.z); v.w = lrelu(v.w); }
        float w = dc * dc;
        acc.x += v.x * w; acc.y += v.y * w; acc.z += v.z * w; acc.w += v.w * w;
    }
    int s0 = __ldg(rowptr + node), s1 = __ldg(rowptr + node + 1);
#pragma unroll 4
    for (int j = s0; j < s1; ++j) {
        int2 p = __ldg(pack + j);                 // uniform per group -> broadcast
        float w = __int_as_float(p.y) * dc;
        float4 v = ldrow<INHALF>(h, (size_t)p.x * TPN + sub);
        if (AFFINE) {
            v.x = v.x * sc.x + sh.x; v.y = v.y * sc.y + sh.y;
            v.z = v.z * sc.z + sh.z; v.w = v.w * sc.w + sh.w;
        }
        if (RELUIN) { v.x = lrelu(v.x); v.y = lrelu(v.y); v.z = lrelu(v.z); v.w = lrelu(v.w); }
        acc.x += v.x * w; acc.y += v.y * w; acc.z += v.z * w; acc.w += v.w * w;
    }
    ((float4*)out)[(size_t)node * TPN + sub] = acc;
}

// ---------------- GAT ----------------
template <int D, int H, bool INHALF>
__global__ void k_gat_scores(const void* __restrict__ h2,
                             const float* __restrict__ a_src, const float* __restrict__ a_dst,
                             float* __restrict__ ss, float* __restrict__ sd, int n) {
    constexpr int C  = D / H;
    constexpr int L  = D / 4;
    constexpr int GP = C / 4;
    int warp = (blockIdx.x * blockDim.x + threadIdx.x) >> 5;
    int lane = threadIdx.x & 31;
    if (warp >= n) return;
    float ps = 0.f, pd = 0.f;
    int head = 0;
    if (lane < L) {
        float4 v = ldrow<INHALF>(h2, (size_t)warp * L + lane);
        head = lane / GP;
        int o = head * C + (lane % GP) * 4;
        ps = v.x * __ldg(a_src + o) + v.y * __ldg(a_src + o + 1)
           + v.z * __ldg(a_src + o + 2) + v.w * __ldg(a_src + o + 3);
        pd = v.x * __ldg(a_dst + o) + v.y * __ldg(a_dst + o + 1)
           + v.z * __ldg(a_dst + o + 2) + v.w * __ldg(a_dst + o + 3);
    }
#pragma unroll
    for (int off = GP / 2; off > 0; off >>= 1) {
        ps += __shfl_xor_sync(0xffffffff, ps, off);
        pd += __shfl_xor_sync(0xffffffff, pd, off);
    }
    if (lane < L && (lane % GP) == 0) {
        ss[(size_t)warp * H + head] = ps;
        sd[(size_t)warp * H + head] = pd;
    }
}

#define NEG_BIG -1e30f
__device__ __forceinline__ void online_upd(float& m, float& s, float e) {
    float nm = fmaxf(m, e);
    s = s * __expf(m - nm) + __expf(e - nm);
    m = nm;
}
__device__ __forceinline__ void online_comb(float& m, float& s, float m2, float s2) {
    float nm = fmaxf(m, m2);
    s = s * __expf(m - nm) + s2 * __expf(m2 - nm);
    m = nm;
}

__global__ void k_gat_softmax(const int* __restrict__ rowptr, const int2* __restrict__ pack,
                              const float* __restrict__ ss, const float* __restrict__ sd,
                              float* __restrict__ mout, float* __restrict__ wsout, int n) {
    int warp = (blockIdx.x * blockDim.x + threadIdx.x) >> 5;
    int lane = threadIdx.x & 31;
    if (warp >= n) return;
    float4 sdv = ((const float4*)sd)[warp];
    float4 m = make_float4(NEG_BIG, NEG_BIG, NEG_BIG, NEG_BIG);
    float4 s = make_float4(0.f, 0.f, 0.f, 0.f);
    if (lane == 0) {
        float4 e = ((const float4*)ss)[warp];
        m.x = lrelu(e.x + sdv.x); m.y = lrelu(e.y + sdv.y);
        m.z = lrelu(e.z + sdv.z); m.w = lrelu(e.w + sdv.w);
        s = make_float4(1.f, 1.f, 1.f, 1.f);
    }
    int s0 = __ldg(rowptr + warp), s1 = __ldg(rowptr + warp + 1);
    for (int j = s0 + lane; j < s1; j += 32) {
        int r = __ldg(pack + j).x;
        float4 e = __ldg((const float4*)ss + r);
        online_upd(m.x, s.x, lrelu(e.x + sdv.x));
        online_upd(m.y, s.y, lrelu(e.y + sdv.y));
        online_upd(m.z, s.z, lrelu(e.z + sdv.z));
        online_upd(m.w, s.w, lrelu(e.w + sdv.w));
    }
#pragma unroll
    for (int off = 16; off > 0; off >>= 1) {
        float m2x = __shfl_xor_sync(0xffffffff, m.x, off);
        float m2y = __shfl_xor_sync(0xffffffff, m.y, off);
        float m2z = __shfl_xor_sync(0xffffffff, m.z, off);
        float m2w = __shfl_xor_sync(0xffffffff, m.w, off);
        float s2x = __shfl_xor_sync(0xffffffff, s.x, off);
        float s2y = __shfl_xor_sync(0xffffffff, s.y, off);
        float s2z = __shfl_xor_sync(0xffffffff, s.z, off);
        float s2w = __shfl_xor_sync(0xffffffff, s.w, off);
        online_comb(m.x, s.x, m2x, s2x);
        online_comb(m.y, s.y, m2y, s2y);
        online_comb(m.z, s.z, m2z, s2z);
        online_comb(m.w, s.w, m2w, s2w);
    }
    if (lane == 0) {
        ((float4*)mout)[warp] = m;
        ((float4*)wsout)[warp] = s;
    }
}

// fused weighted gather + bias + affine(residual) + lrelu; fp16 h2 in, fp16/fp32 out
template <int TPN, int H, bool RELU, bool INHALF, bool OUTHALF>
__global__ void __launch_bounds__(256)
k_gat_fused(const int* __restrict__ rowptr, const int2* __restrict__ pack,
            const float* __restrict__ ss, const float* __restrict__ sd,
            const float* __restrict__ m_, const float* __restrict__ ws_,
            const void* __restrict__ h2, const float* __restrict__ bias,
            const float* __restrict__ resraw,
            const float* __restrict__ sc_, const float* __restrict__ sh_,
            void* __restrict__ outv, int n) {
    constexpr int C = TPN * 4 / H;
    int t = blockIdx.x * 256 + threadIdx.x;
    int node = t / TPN, sub = t % TPN;
    if (node >= n) return;
    int head = (sub * 4) / C;
    float sdv = __ldg(sd + (size_t)node * H + head);
    float m   = __ldg(m_ + (size_t)node * H + head);
    float inv = 1.0f / __ldg(ws_ + (size_t)node * H + head);

    float wsf = __expf(lrelu(__ldg(ss + (size_t)node * H + head) + sdv) - m);
    float4 acc = ldrow<INHALF>(h2, (size_t)node * TPN + sub);
    acc.x *= wsf; acc.y *= wsf; acc.z *= wsf; acc.w *= wsf;

    int s0 = __ldg(rowptr + node), s1 = __ldg(rowptr + node + 1);
#pragma unroll 4
    for (int j = s0; j < s1; ++j) {
        int r = __ldg(pack + j).x;
        float e = lrelu(__ldg(ss + (size_t)r * H + head) + sdv);
        float w = __expf(e - m);
        float4 v = ldrow<INHALF>(h2, (size_t)r * TPN + sub);
        acc.x += v.x * w; acc.y += v.y * w; acc.z += v.z * w; acc.w += v.w * w;
    }
    float4 bv = __ldg((const float4*)bias + sub);
    float4 xr = __ldg((const float4*)resraw + (size_t)node * TPN + sub);
    float4 sc = __ldg((const float4*)sc_ + sub);
    float4 sh = __ldg((const float4*)sh_ + sub);
    float4 o;
    o.x = acc.x * inv + bv.x + (xr.x * sc.x + sh.x);
    o.y = acc.y * inv + bv.y + (xr.y * sc.y + sh.y);
    o.z = acc.z * inv + bv.z + (xr.z * sc.z + sh.z);
    o.w = acc.w * inv + bv.w + (xr.w * sc.w + sh.w);
    if (RELU) { o.x = lrelu(o.x); o.y = lrelu(o.y); o.z = lrelu(o.z); o.w = lrelu(o.w); }
    if (OUTHALF) st4half(outv, (size_t)node * TPN + sub, o);
    else ((float4*)outv)[(size_t)node * TPN + sub] = o;
}

// ---------------- pooling (final-layer affine applied on read) ----------------
__global__ void k_pool_clear(float* out, float* cnt, int total, int G) {
    int i = blockIdx.x * blockDim.x + threadIdx.x;
    if (i < total) out[i] = 0.f;
    if (i < G) cnt[i] = 0.f;
}
__global__ void k_pool_sum(const float* __restrict__ x, const int* __restrict__ batch,
                           const float* __restrict__ sc_, const float* __restrict__ sh_,
                           float* __restrict__ out, float* cnt, int n) {
    int idx = blockIdx.x * blockDim.x + threadIdx.x;
    if (idx >= n * 16) return;
    int nn = idx / 16, cg = idx % 16;
    int g = __ldg(batch + nn);
    float4 v = ((const float4*)x)[idx];
    float4 sc = __ldg((const float4*)sc_ + cg);
    float4 sh = __ldg((const float4*)sh_ + cg);
    v.x = v.x * sc.x + sh.x; v.y = v.y * sc.y + sh.y;
    v.z = v.z * sc.z + sh.z; v.w = v.w * sc.w + sh.w;
    atomicAdd((float4*)out + (size_t)g * 16 + cg, v);
    if (cg == 0) atomicAdd(&cnt[g], 1.0f);
}
__global__ void k_pool_div(float* out, const float* cnt, int total) {
    int i = blockIdx.x * blockDim.x + threadIdx.x;
    if (i >= total) return;
    int g = i / 64;
    out[i] /= fmaxf(cnt[g], 1.0f);
}

// ---------------- host ----------------
static inline int GRID(long long t) { return (int)((t + 255) / 256); }

extern "C" void kernel_launch(void* const* d_in, const int* in_sizes, int n_in,
                              void* d_out, int out_size) {
    const float* x     = (const float*)d_in[0];
    const int*   ei    = (const int*)d_in[1];
    const int*   batch = (const int*)d_in[2];
    const int n = in_sizes[0] / 16;
    const int E = in_sizes[1] / 2;
    const int* rowp = ei;
    const int* colp = ei + E;

    const float* gcn_w[4] = {(const float*)d_in[3], (const float*)d_in[7],
                             (const float*)d_in[11], (const float*)d_in[15]};
    const float* gcn_b[4] = {(const float*)d_in[4], (const float*)d_in[8],
                             (const float*)d_in[12], (const float*)d_in[16]};
    const float* bn_g[4]  = {(const float*)d_in[5], (const float*)d_in[9],
                             (const float*)d_in[13], (const float*)d_in[17]};
    const float* bn_b[4]  = {(const float*)d_in[6], (const float*)d_in[10],
                             (const float*)d_in[14], (const float*)d_in[18]};
    const float* gat_w0    = (const float*)d_in[19];
    const float* gat_asrc0 = (const float*)d_in[20];
    const float* gat_adst0 = (const float*)d_in[21];
    const float* gat_b0    = (const float*)d_in[22];
    const float* gat_w2    = (const float*)d_in[23];
    const float* gat_asrc2 = (const float*)d_in[24];
    const float* gat_adst2 = (const float*)d_in[25];
    const float* gat_b2    = (const float*)d_in[26];

    float *A, *B, *C, *dis, *ss, *sd, *mM, *wsum, *mean, *sq, *scale, *shift, *cnt;
    __half *Hh, *H2h;
    int *deg, *rowptr, *cursor, *blksum;
    int2* pack;
    cudaGetSymbolAddress((void**)&A, g_A);
    cudaGetSymbolAddress((void**)&B, g_B);
    cudaGetSymbolAddress((void**)&C, g_C);
    cudaGetSymbolAddress((void**)&Hh, g_H);
    cudaGetSymbolAddress((void**)&H2h, g_H2);
    cudaGetSymbolAddress((void**)&dis, g_dis);
    cudaGetSymbolAddress((void**)&deg, g_deg);
    cudaGetSymbolAddress((void**)&rowptr, g_rowptr);
    cudaGetSymbolAddress((void**)&cursor, g_cursor);
    cudaGetSymbolAddress((void**)&pack, g_pack);
    cudaGetSymbolAddress((void**)&blksum, g_blksum);
    cudaGetSymbolAddress((void**)&ss, g_ss);
    cudaGetSymbolAddress((void**)&sd, g_sd);
    cudaGetSymbolAddress((void**)&mM, g_m);
    cudaGetSymbolAddress((void**)&wsum, g_ws);
    cudaGetSymbolAddress((void**)&mean, g_mean);
    cudaGetSymbolAddress((void**)&sq, g_sq);
    cudaGetSymbolAddress((void**)&scale, g_scale);
    cudaGetSymbolAddress((void**)&shift, g_shift);
    cudaGetSymbolAddress((void**)&cnt, g_cnt);
    float* out = (float*)d_out;

    // ---- CSR build: 5 launches (scan2 fused into scan3) ----
    const int nb = (n + SCAN_CHUNK - 1) / SCAN_CHUNK;
    k_deg_zero<<<GRID(n), 256>>>(deg, n);
    k_deg_count<<<GRID(E), 256>>>(colp, deg, E);
    k_scan1<<<nb, SCAN_CHUNK>>>(deg, blksum, n);
    k_scan3_dis<<<nb, SCAN_CHUNK>>>(deg, blksum, rowptr, cursor, dis, n);
    k_csr_fill<<<GRID(E), 256>>>(rowp, colp, dis, cursor, pack, E);

    // ----- layer 0 -----
    k_gather<4, false, false, false, false><<<(n + 63) / 64, 256>>>(
        rowptr, pack, dis, x, nullptr, nullptr, nullptr, C, n);
    k_gemm<16, 64, true, false, false><<<(n + 127) / 128, 256>>>(
        C, gcn_w[0], gcn_b[0], nullptr, nullptr, B, n);
    k_bn_partial<64, false><<<(n + 63) / 64, 256>>>(B, mean, sq, n);
    k_bn_final<64><<<1, 64>>>(mean, sq, bn_g[0], bn_b[0], scale, shift, n);
    k_gemm<64, 64, false, true, true><<<(n + 127) / 128, 256>>>(
        B, gat_w0, nullptr, scale, shift, H2h, n);
    k_gat_scores<64, 4, true><<<(n + 3) / 4, 128>>>(H2h, gat_asrc0, gat_adst0, ss, sd, n);
    k_gat_softmax<<<(n + 7) / 8, 256>>>(rowptr, pack, ss, sd, mM, wsum, n);
    k_gat_fused<16, 4, true, true, true><<<(n + 15) / 16, 256>>>(
        rowptr, pack, ss, sd, mM, wsum, H2h, gat_b0, B, scale, shift, Hh, n);

    // ----- layer 1 (gather fp16 input) -----
    k_gather<16, false, false, false, true><<<(n + 15) / 16, 256>>>(
        rowptr, pack, dis, Hh, nullptr, nullptr, nullptr, C, n);
    k_gemm<64, 128, true, false, true><<<(n + 63) / 64, 256>>>(
        C, gcn_w[1], gcn_b[1], nullptr, nullptr, Hh, n);
    k_bn_partial<128, true><<<(n + 63) / 64, 256>>>(Hh, mean, sq, n);
    k_bn_final<128><<<1, 128>>>(mean, sq, bn_g[1], bn_b[1], scale, shift, n);

    // ----- layer 2 (L1 bn+relu folded into fp16 gather input) -----
    k_gather<32, false, true, true, true><<<(n + 7) / 8, 256>>>(
        rowptr, pack, dis, Hh, nullptr, scale, shift, C, n);
    k_gemm<128, 128, true, false, false><<<(n + 63) / 64, 256>>>(
        C, gcn_w[2], gcn_b[2], nullptr, nullptr, B, n);
    k_bn_partial<128, false><<<(n + 63) / 64, 256>>>(B, mean, sq, n);
    k_bn_final<128><<<1, 128>>>(mean, sq, bn_g[2], bn_b[2], scale, shift, n);
    k_gemm<128, 128, false, true, true><<<(n + 63) / 64, 256>>>(
        B, gat_w2, nullptr, scale, shift, Hh, n);
    k_gat_scores<128, 4, true><<<(n + 3) / 4, 128>>>(Hh, gat_asrc2, gat_adst2, ss, sd, n);
    k_gat_softmax<<<(n + 7) / 8, 256>>>(rowptr, pack, ss, sd, mM, wsum, n);
    k_gat_fused<32, 4, true, true, false><<<(n + 7) / 8, 256>>>(
        rowptr, pack, ss, sd, mM, wsum, Hh, gat_b2, B, scale, shift, A, n);

    // ----- layer 3 -----
    k_gemm<128, 64, false, false, true><<<(n + 127) / 128, 256>>>(
        A, gcn_w[3], nullptr, nullptr, nullptr, H2h, n);
    k_gather<16, true, false, false, true><<<(n + 15) / 16, 256>>>(
        rowptr, pack, dis, H2h, gcn_b[3], nullptr, nullptr, C, n);
    k_bn_partial<64, false><<<(n + 63) / 64, 256>>>(C, mean, sq, n);
    k_bn_final<64><<<1, 64>>>(mean, sq, bn_g[3], bn_b[3], scale, shift, n);

    // ----- pooling -----
    const int G = out_size / 64;
    k_pool_clear<<<GRID(out_size), 256>>>(out, cnt, out_size, G);
    k_pool_sum<<<GRID((long long)n * 16), 256>>>(C, batch, scale, shift, out, cnt, n);
    k_pool_div<<<GRID(out_size), 256>>>(out, cnt, out_size);
}